// round 1
// baseline (speedup 1.0000x reference)
#include <cuda_runtime.h>
#include <math.h>

#define BATCH 4
#define SEQ   2048
#define DIM   512
#define HEADS 8
#define DHEAD 64
#define QKVC  1536
#define MTOT  (BATCH * SEQ)   // 8192
#define LD    68              // padded smem row (64 + 4, keeps float4 alignment)

// Scratch (no cudaMalloc allowed): qkv projection output + attention output
__device__ float g_qkv[(size_t)MTOT * QKVC];  // ~50 MB
__device__ float g_att[(size_t)MTOT * DIM];   // ~17 MB

// ---------------------------------------------------------------------------
// C[M,N] = A[M,K] @ B[N,K]^T   (both A and B are K-contiguous row-major)
// 128x128 block tile, BK=8, 256 threads, 8x8 per thread.
// ---------------------------------------------------------------------------
__global__ __launch_bounds__(256) void sgemm_abt(
    const float* __restrict__ A, const float* __restrict__ B,
    float* __restrict__ C, int M, int N, int K)
{
    __shared__ float As[8][128];
    __shared__ float Bs[8][128];

    const int tid = threadIdx.x;
    const int m0 = blockIdx.y * 128;
    const int n0 = blockIdx.x * 128;
    const int ty = tid >> 4;        // 0..15
    const int tx = tid & 15;        // 0..15
    const int lr = tid >> 1;        // 0..127 (load row)
    const int lk = (tid & 1) * 4;   // 0 or 4 (load k offset)

    float acc[8][8];
#pragma unroll
    for (int i = 0; i < 8; i++)
#pragma unroll
        for (int j = 0; j < 8; j++) acc[i][j] = 0.f;

    const float* Ap = A + (size_t)(m0 + lr) * K + lk;
    const float* Bp = B + (size_t)(n0 + lr) * K + lk;

    for (int k0 = 0; k0 < K; k0 += 8) {
        float4 a4 = *(const float4*)(Ap + k0);
        float4 b4 = *(const float4*)(Bp + k0);
        __syncthreads();
        As[lk + 0][lr] = a4.x; As[lk + 1][lr] = a4.y;
        As[lk + 2][lr] = a4.z; As[lk + 3][lr] = a4.w;
        Bs[lk + 0][lr] = b4.x; Bs[lk + 1][lr] = b4.y;
        Bs[lk + 2][lr] = b4.z; Bs[lk + 3][lr] = b4.w;
        __syncthreads();

#pragma unroll
        for (int kk = 0; kk < 8; kk++) {
            float a[8], b[8];
            *(float4*)&a[0] = *(const float4*)&As[kk][ty * 8];
            *(float4*)&a[4] = *(const float4*)&As[kk][ty * 8 + 4];
            *(float4*)&b[0] = *(const float4*)&Bs[kk][tx * 8];
            *(float4*)&b[4] = *(const float4*)&Bs[kk][tx * 8 + 4];
#pragma unroll
            for (int i = 0; i < 8; i++)
#pragma unroll
                for (int j = 0; j < 8; j++)
                    acc[i][j] = fmaf(a[i], b[j], acc[i][j]);
        }
    }

#pragma unroll
    for (int i = 0; i < 8; i++) {
        float* cp = C + (size_t)(m0 + ty * 8 + i) * N + n0 + tx * 8;
        *(float4*)cp       = make_float4(acc[i][0], acc[i][1], acc[i][2], acc[i][3]);
        *(float4*)(cp + 4) = make_float4(acc[i][4], acc[i][5], acc[i][6], acc[i][7]);
    }
}

// ---------------------------------------------------------------------------
// Flash attention, fp32. One block = (b,h) x 64-query tile. 256 threads.
// Qt/Kt stored d-major (transposed), Vs row-major, Pt key-major — all inner
// smem reads are conflict-free float4.
// ---------------------------------------------------------------------------
__global__ __launch_bounds__(256) void flash_attn(
    const float* __restrict__ qkv, float* __restrict__ out)
{
    extern __shared__ float sm[];
    float* Qt = sm;               // Qt[d*LD + r]  (pre-scaled)
    float* Kt = Qt + 64 * LD;     // Kt[d*LD + c]
    float* Vs = Kt + 64 * LD;     // Vs[c*LD + d]
    float* Pt = Vs + 64 * LD;     // Pt[c*LD + r]

    const int tid = threadIdx.x;
    const int bh  = blockIdx.y;
    const int b   = bh >> 3;
    const int h   = bh & 7;
    const int q0  = blockIdx.x * 64;
    const int ty  = tid >> 4, tx = tid & 15;
    const int r0  = ty * 4;   // query rows owned
    const int c0  = tx * 4;   // key cols owned (S phase)
    const int d0  = tx * 4;   // head dims owned (O phase)

    const int lrow = tid >> 2;          // 0..63
    const int lseg = (tid & 3) << 4;    // 0,16,32,48
    const float scale = 0.125f;         // 64^-0.5

    // Load Q tile (scaled) transposed into Qt
    {
        const float* qp = qkv + (size_t)(b * SEQ + q0 + lrow) * QKVC + h * DHEAD + lseg;
#pragma unroll
        for (int t = 0; t < 4; t++) {
            float4 v = *(const float4*)(qp + t * 4);
            int d = lseg + t * 4;
            Qt[(d + 0) * LD + lrow] = v.x * scale;
            Qt[(d + 1) * LD + lrow] = v.y * scale;
            Qt[(d + 2) * LD + lrow] = v.z * scale;
            Qt[(d + 3) * LD + lrow] = v.w * scale;
        }
    }

    float m_i[4], l_i[4], o[4][4];
#pragma unroll
    for (int i = 0; i < 4; i++) {
        m_i[i] = -INFINITY;
        l_i[i] = 0.f;
#pragma unroll
        for (int j = 0; j < 4; j++) o[i][j] = 0.f;
    }

    for (int jt = 0; jt < SEQ / 64; jt++) {
        __syncthreads();  // previous PV done reading Vs/Pt
        // Load K (transposed) and V (row-major) tiles
        {
            const float* kp = qkv + (size_t)(b * SEQ + jt * 64 + lrow) * QKVC
                              + 512 + h * DHEAD + lseg;
            const float* vp = kp + 512;
#pragma unroll
            for (int t = 0; t < 4; t++) {
                float4 kv = *(const float4*)(kp + t * 4);
                int d = lseg + t * 4;
                Kt[(d + 0) * LD + lrow] = kv.x;
                Kt[(d + 1) * LD + lrow] = kv.y;
                Kt[(d + 2) * LD + lrow] = kv.z;
                Kt[(d + 3) * LD + lrow] = kv.w;
                *(float4*)&Vs[lrow * LD + d] = *(const float4*)(vp + t * 4);
            }
        }
        __syncthreads();

        // S = (Q*scale) @ K^T, 4x4 per thread
        float s[4][4];
#pragma unroll
        for (int i = 0; i < 4; i++)
#pragma unroll
            for (int j = 0; j < 4; j++) s[i][j] = 0.f;

#pragma unroll 8
        for (int d = 0; d < 64; d++) {
            float4 qv = *(const float4*)&Qt[d * LD + r0];
            float4 kv = *(const float4*)&Kt[d * LD + c0];
            float qa[4] = {qv.x, qv.y, qv.z, qv.w};
            float ka[4] = {kv.x, kv.y, kv.z, kv.w};
#pragma unroll
            for (int i = 0; i < 4; i++)
#pragma unroll
                for (int j = 0; j < 4; j++)
                    s[i][j] = fmaf(qa[i], ka[j], s[i][j]);
        }

        // Online softmax per query row (reduce across the 16 tx lanes)
#pragma unroll
        for (int i = 0; i < 4; i++) {
            float mloc = fmaxf(fmaxf(s[i][0], s[i][1]), fmaxf(s[i][2], s[i][3]));
#pragma unroll
            for (int ofs = 1; ofs < 16; ofs <<= 1)
                mloc = fmaxf(mloc, __shfl_xor_sync(0xffffffffu, mloc, ofs));
            float mnew = fmaxf(m_i[i], mloc);
            float corr = __expf(m_i[i] - mnew);
            m_i[i] = mnew;
            float psum = 0.f;
#pragma unroll
            for (int j = 0; j < 4; j++) {
                float p = __expf(s[i][j] - mnew);
                Pt[(c0 + j) * LD + (r0 + i)] = p;
                psum += p;
            }
#pragma unroll
            for (int ofs = 1; ofs < 16; ofs <<= 1)
                psum += __shfl_xor_sync(0xffffffffu, psum, ofs);
            l_i[i] = l_i[i] * corr + psum;
#pragma unroll
            for (int j = 0; j < 4; j++) o[i][j] *= corr;
        }
        __syncthreads();  // Pt visible

        // O += P @ V
#pragma unroll 8
        for (int c = 0; c < 64; c++) {
            float4 pv = *(const float4*)&Pt[c * LD + r0];
            float4 vv = *(const float4*)&Vs[c * LD + d0];
            float pa[4] = {pv.x, pv.y, pv.z, pv.w};
            float va[4] = {vv.x, vv.y, vv.z, vv.w};
#pragma unroll
            for (int i = 0; i < 4; i++)
#pragma unroll
                for (int j = 0; j < 4; j++)
                    o[i][j] = fmaf(pa[i], va[j], o[i][j]);
        }
    }

    // Normalize and write out[b, q, h*64 + d]
#pragma unroll
    for (int i = 0; i < 4; i++) {
        float inv = 1.f / l_i[i];
        float* op = out + (size_t)(b * SEQ + q0 + r0 + i) * DIM + h * DHEAD + d0;
        *(float4*)op = make_float4(o[i][0] * inv, o[i][1] * inv,
                                   o[i][2] * inv, o[i][3] * inv);
    }
}

// ---------------------------------------------------------------------------
extern "C" void kernel_launch(void* const* d_in, const int* in_sizes, int n_in,
                              void* d_out, int out_size)
{
    const float* x    = (const float*)d_in[0];  // [4, 2048, 512]
    const float* Wqkv = (const float*)d_in[1];  // [1536, 512]
    const float* Wout = (const float*)d_in[2];  // [512, 512]
    float* out = (float*)d_out;                 // [4, 2048, 512]

    float* qkvbuf = nullptr;
    float* attbuf = nullptr;
    cudaGetSymbolAddress((void**)&qkvbuf, g_qkv);
    cudaGetSymbolAddress((void**)&attbuf, g_att);

    const int smem_flash = 4 * 64 * LD * (int)sizeof(float);  // 69632 B
    cudaFuncSetAttribute(flash_attn,
                         cudaFuncAttributeMaxDynamicSharedMemorySize, smem_flash);

    // 1) QKV projection: [8192,512] @ [1536,512]^T -> [8192,1536]
    sgemm_abt<<<dim3(QKVC / 128, MTOT / 128), 256>>>(x, Wqkv, qkvbuf, MTOT, QKVC, DIM);

    // 2) Flash attention per (b,h), 64-query tiles -> [8192,512]
    flash_attn<<<dim3(SEQ / 64, BATCH * HEADS), 256, smem_flash>>>(qkvbuf, attbuf);

    // 3) Output projection: [8192,512] @ [512,512]^T -> [8192,512]
    sgemm_abt<<<dim3(DIM / 128, MTOT / 128), 256>>>(attbuf, Wout, out, MTOT, DIM, DIM);
}

// round 3
// speedup vs baseline: 1.2018x; 1.2018x over previous
#include <cuda_runtime.h>
#include <cuda_bf16.h>
#include <cstdint>
#include <math.h>

#define BATCH 4
#define SEQ   2048
#define DIM   512
#define HEADS 8
#define DHEAD 64
#define QKVC  1536
#define MTOT  (BATCH * SEQ)   // 8192
#define LD    68

// ---------------------------------------------------------------------------
// Scratch (__device__ globals; 16B-aligned for vector/cp.async access)
// ---------------------------------------------------------------------------
__device__ __align__(16) float g_qkv[(size_t)MTOT * QKVC];
__device__ __align__(16) float g_att[(size_t)MTOT * DIM];
__device__ __align__(16) __nv_bfloat16 g_xhi[(size_t)MTOT * DIM];
__device__ __align__(16) __nv_bfloat16 g_xlo[(size_t)MTOT * DIM];
__device__ __align__(16) __nv_bfloat16 g_whi[(size_t)QKVC * DIM];
__device__ __align__(16) __nv_bfloat16 g_wlo[(size_t)QKVC * DIM];
__device__ __align__(16) __nv_bfloat16 g_uhi[(size_t)DIM * DIM];
__device__ __align__(16) __nv_bfloat16 g_ulo[(size_t)DIM * DIM];
__device__ __align__(16) __nv_bfloat16 g_ahi[(size_t)MTOT * DIM];
__device__ __align__(16) __nv_bfloat16 g_alo[(size_t)MTOT * DIM];

__device__ __forceinline__ uint32_t smem_u32(const void* p) {
    uint32_t a;
    asm("{ .reg .u64 t; cvta.to.shared.u64 t, %1; cvt.u32.u64 %0, t; }"
        : "=r"(a) : "l"(p));
    return a;
}

__device__ __forceinline__ void ldmatrix_x4(
    uint32_t& r0, uint32_t& r1, uint32_t& r2, uint32_t& r3, uint32_t addr)
{
    asm volatile("ldmatrix.sync.aligned.m8n8.x4.shared.b16 {%0,%1,%2,%3}, [%4];"
                 : "=r"(r0), "=r"(r1), "=r"(r2), "=r"(r3) : "r"(addr));
}

__device__ __forceinline__ void mma_bf16(
    float& d0, float& d1, float& d2, float& d3,
    uint32_t a0, uint32_t a1, uint32_t a2, uint32_t a3,
    uint32_t b0, uint32_t b1)
{
    asm volatile(
        "mma.sync.aligned.m16n8k16.row.col.f32.bf16.bf16.f32 "
        "{%0,%1,%2,%3}, {%4,%5,%6,%7}, {%8,%9}, {%0,%1,%2,%3};"
        : "+f"(d0), "+f"(d1), "+f"(d2), "+f"(d3)
        : "r"(a0), "r"(a1), "r"(a2), "r"(a3), "r"(b0), "r"(b1));
}

__device__ __forceinline__ void cp_async16(uint32_t dst, const void* src) {
    asm volatile("cp.async.cg.shared.global [%0], [%1], 16;" :: "r"(dst), "l"(src));
}

// ---------------------------------------------------------------------------
// fp32 -> (hi bf16, lo bf16) split
// ---------------------------------------------------------------------------
__global__ __launch_bounds__(256) void split_f32(
    const float4* __restrict__ in, __nv_bfloat16* __restrict__ hi,
    __nv_bfloat16* __restrict__ lo, int n4)
{
    int i = blockIdx.x * 256 + threadIdx.x;
    if (i >= n4) return;
    float4 v = in[i];
    float xs[4] = {v.x, v.y, v.z, v.w};
    __nv_bfloat16 h[4], l[4];
#pragma unroll
    for (int j = 0; j < 4; j++) {
        h[j] = __float2bfloat16_rn(xs[j]);
        l[j] = __float2bfloat16_rn(xs[j] - __bfloat162float(h[j]));
    }
    *(uint2*)(hi + 4 * (size_t)i) = *(uint2*)h;
    *(uint2*)(lo + 4 * (size_t)i) = *(uint2*)l;
}

// ---------------------------------------------------------------------------
// mma.sync split-bf16 GEMM: C[M,N] = A[M,K] @ B[N,K]^T  (fp32-accurate)
// 128x128 CTA tile, 8 warps (2x4 -> 64x32 warp tiles), BK=32,
// cp.async double-buffered smem, 80B row stride (conflict-free ldmatrix).
// ---------------------------------------------------------------------------
#define LDS_T   40                    // smem row stride in bf16 elems (80 B)
#define TILE_E  (128 * LDS_T)         // elems per 128x32 tile buffer
#define GEMM_SMEM (2 * 4 * TILE_E * 2)  // 81920 B

__global__ __launch_bounds__(256, 1) void gemm_mma(
    const __nv_bfloat16* __restrict__ Ahi, const __nv_bfloat16* __restrict__ Alo,
    const __nv_bfloat16* __restrict__ Bhi, const __nv_bfloat16* __restrict__ Blo,
    float* __restrict__ C, int M, int N, int K)
{
    extern __shared__ __nv_bfloat16 sm[];
    const uint32_t sbase = smem_u32(sm);

    const int tid  = threadIdx.x;
    const int wid  = tid >> 5;
    const int lane = tid & 31;
    const int warp_m = wid >> 2;      // 0..1 -> 64-row slabs
    const int warp_n = wid & 3;       // 0..3 -> 32-col slabs
    const int m0 = blockIdx.y * 128;
    const int n0 = blockIdx.x * 128;

    const __nv_bfloat16* srcs[4] = {
        Ahi + (size_t)m0 * K, Alo + (size_t)m0 * K,
        Bhi + (size_t)n0 * K, Blo + (size_t)n0 * K };

    // ldmatrix per-lane row/k-offset (identical pattern for A and B x4 loads)
    const int lr   = lane & 15;                 // row within 16-row fragment
    const int kofs = (lane & 16) ? 8 : 0;       // k offset within 16

    float acc[4][4][4];
#pragma unroll
    for (int mi = 0; mi < 4; mi++)
#pragma unroll
        for (int ni = 0; ni < 4; ni++)
#pragma unroll
            for (int r = 0; r < 4; r++) acc[mi][ni][r] = 0.f;

    const int nchunks = K / 32;       // 16

    // issue one stage of cp.async loads (4 tiles x 128x32 bf16)
    auto issue_stage = [&](int st, int k0) {
#pragma unroll
        for (int t = 0; t < 4; t++) {
#pragma unroll
            for (int q = 0; q < 2; q++) {
                int v   = tid + q * 256;        // 0..511
                int row = v >> 2;
                int kv  = v & 3;
                uint32_t dst = sbase +
                    (uint32_t)(((st * 4 + t) * TILE_E + row * LDS_T + kv * 8) * 2);
                cp_async16(dst, srcs[t] + (size_t)row * K + k0 + kv * 8);
            }
        }
        asm volatile("cp.async.commit_group;");
    };

    issue_stage(0, 0);

    for (int c = 0; c < nchunks; c++) {
        if (c + 1 < nchunks) {
            issue_stage((c + 1) & 1, (c + 1) * 32);
            asm volatile("cp.async.wait_group 1;");
        } else {
            asm volatile("cp.async.wait_group 0;");
        }
        __syncthreads();

        const uint32_t stb = sbase + (uint32_t)(((c & 1) * 4) * TILE_E * 2);

#pragma unroll
        for (int ks = 0; ks < 32; ks += 16) {
            uint32_t Ahif[4][4], Alof[4][4];
#pragma unroll
            for (int mi = 0; mi < 4; mi++) {
                int row = warp_m * 64 + mi * 16 + lr;
                uint32_t a0 = stb + (uint32_t)((0 * TILE_E + row * LDS_T + ks + kofs) * 2);
                uint32_t a1 = stb + (uint32_t)((1 * TILE_E + row * LDS_T + ks + kofs) * 2);
                ldmatrix_x4(Ahif[mi][0], Ahif[mi][1], Ahif[mi][2], Ahif[mi][3], a0);
                ldmatrix_x4(Alof[mi][0], Alof[mi][1], Alof[mi][2], Alof[mi][3], a1);
            }
            uint32_t Bhif[4][2], Blof[4][2];
#pragma unroll
            for (int bi = 0; bi < 2; bi++) {
                int row = warp_n * 32 + bi * 16 + lr;
                uint32_t b0 = stb + (uint32_t)((2 * TILE_E + row * LDS_T + ks + kofs) * 2);
                uint32_t b1 = stb + (uint32_t)((3 * TILE_E + row * LDS_T + ks + kofs) * 2);
                uint32_t r0, r1, r2, r3;
                ldmatrix_x4(r0, r1, r2, r3, b0);
                Bhif[bi * 2][0] = r0; Bhif[bi * 2][1] = r2;
                Bhif[bi * 2 + 1][0] = r1; Bhif[bi * 2 + 1][1] = r3;
                ldmatrix_x4(r0, r1, r2, r3, b1);
                Blof[bi * 2][0] = r0; Blof[bi * 2][1] = r2;
                Blof[bi * 2 + 1][0] = r1; Blof[bi * 2 + 1][1] = r3;
            }
#pragma unroll
            for (int mi = 0; mi < 4; mi++) {
#pragma unroll
                for (int ni = 0; ni < 4; ni++) {
                    float* d = acc[mi][ni];
                    mma_bf16(d[0], d[1], d[2], d[3],
                             Ahif[mi][0], Ahif[mi][1], Ahif[mi][2], Ahif[mi][3],
                             Bhif[ni][0], Bhif[ni][1]);
                    mma_bf16(d[0], d[1], d[2], d[3],
                             Ahif[mi][0], Ahif[mi][1], Ahif[mi][2], Ahif[mi][3],
                             Blof[ni][0], Blof[ni][1]);
                    mma_bf16(d[0], d[1], d[2], d[3],
                             Alof[mi][0], Alof[mi][1], Alof[mi][2], Alof[mi][3],
                             Bhif[ni][0], Bhif[ni][1]);
                }
            }
        }
        __syncthreads();
    }

    // Epilogue: C-fragment layout -> global fp32
    const int g = lane >> 2, tig = lane & 3;
#pragma unroll
    for (int mi = 0; mi < 4; mi++) {
#pragma unroll
        for (int ni = 0; ni < 4; ni++) {
            int row = m0 + warp_m * 64 + mi * 16 + g;
            int col = n0 + warp_n * 32 + ni * 8 + tig * 2;
            *(float2*)&C[(size_t)row * N + col] =
                make_float2(acc[mi][ni][0], acc[mi][ni][1]);
            *(float2*)&C[(size_t)(row + 8) * N + col] =
                make_float2(acc[mi][ni][2], acc[mi][ni][3]);
        }
    }
}

// ---------------------------------------------------------------------------
// Flash attention, fp32 (unchanged — proven)
// ---------------------------------------------------------------------------
__global__ __launch_bounds__(256) void flash_attn(
    const float* __restrict__ qkv, float* __restrict__ out)
{
    extern __shared__ float smf[];
    float* Qt = smf;
    float* Kt = Qt + 64 * LD;
    float* Vs = Kt + 64 * LD;
    float* Pt = Vs + 64 * LD;

    const int tid = threadIdx.x;
    const int bh  = blockIdx.y;
    const int b   = bh >> 3;
    const int h   = bh & 7;
    const int q0  = blockIdx.x * 64;
    const int ty  = tid >> 4, tx = tid & 15;
    const int r0  = ty * 4;
    const int c0  = tx * 4;
    const int d0  = tx * 4;

    const int lrow = tid >> 2;
    const int lseg = (tid & 3) << 4;
    const float scale = 0.125f;

    {
        const float* qp = qkv + (size_t)(b * SEQ + q0 + lrow) * QKVC + h * DHEAD + lseg;
#pragma unroll
        for (int t = 0; t < 4; t++) {
            float4 v = *(const float4*)(qp + t * 4);
            int d = lseg + t * 4;
            Qt[(d + 0) * LD + lrow] = v.x * scale;
            Qt[(d + 1) * LD + lrow] = v.y * scale;
            Qt[(d + 2) * LD + lrow] = v.z * scale;
            Qt[(d + 3) * LD + lrow] = v.w * scale;
        }
    }

    float m_i[4], l_i[4], o[4][4];
#pragma unroll
    for (int i = 0; i < 4; i++) {
        m_i[i] = -INFINITY;
        l_i[i] = 0.f;
#pragma unroll
        for (int j = 0; j < 4; j++) o[i][j] = 0.f;
    }

    for (int jt = 0; jt < SEQ / 64; jt++) {
        __syncthreads();
        {
            const float* kp = qkv + (size_t)(b * SEQ + jt * 64 + lrow) * QKVC
                              + 512 + h * DHEAD + lseg;
            const float* vp = kp + 512;
#pragma unroll
            for (int t = 0; t < 4; t++) {
                float4 kv = *(const float4*)(kp + t * 4);
                int d = lseg + t * 4;
                Kt[(d + 0) * LD + lrow] = kv.x;
                Kt[(d + 1) * LD + lrow] = kv.y;
                Kt[(d + 2) * LD + lrow] = kv.z;
                Kt[(d + 3) * LD + lrow] = kv.w;
                *(float4*)&Vs[lrow * LD + d] = *(const float4*)(vp + t * 4);
            }
        }
        __syncthreads();

        float s[4][4];
#pragma unroll
        for (int i = 0; i < 4; i++)
#pragma unroll
            for (int j = 0; j < 4; j++) s[i][j] = 0.f;

#pragma unroll 8
        for (int d = 0; d < 64; d++) {
            float4 qv = *(const float4*)&Qt[d * LD + r0];
            float4 kv = *(const float4*)&Kt[d * LD + c0];
            float qa[4] = {qv.x, qv.y, qv.z, qv.w};
            float ka[4] = {kv.x, kv.y, kv.z, kv.w};
#pragma unroll
            for (int i = 0; i < 4; i++)
#pragma unroll
                for (int j = 0; j < 4; j++)
                    s[i][j] = fmaf(qa[i], ka[j], s[i][j]);
        }

#pragma unroll
        for (int i = 0; i < 4; i++) {
            float mloc = fmaxf(fmaxf(s[i][0], s[i][1]), fmaxf(s[i][2], s[i][3]));
#pragma unroll
            for (int ofs = 1; ofs < 16; ofs <<= 1)
                mloc = fmaxf(mloc, __shfl_xor_sync(0xffffffffu, mloc, ofs));
            float mnew = fmaxf(m_i[i], mloc);
            float corr = __expf(m_i[i] - mnew);
            m_i[i] = mnew;
            float psum = 0.f;
#pragma unroll
            for (int j = 0; j < 4; j++) {
                float p = __expf(s[i][j] - mnew);
                Pt[(c0 + j) * LD + (r0 + i)] = p;
                psum += p;
            }
#pragma unroll
            for (int ofs = 1; ofs < 16; ofs <<= 1)
                psum += __shfl_xor_sync(0xffffffffu, psum, ofs);
            l_i[i] = l_i[i] * corr + psum;
#pragma unroll
            for (int j = 0; j < 4; j++) o[i][j] *= corr;
        }
        __syncthreads();

#pragma unroll 8
        for (int c = 0; c < 64; c++) {
            float4 pv = *(const float4*)&Pt[c * LD + r0];
            float4 vv = *(const float4*)&Vs[c * LD + d0];
            float pa[4] = {pv.x, pv.y, pv.z, pv.w};
            float va[4] = {vv.x, vv.y, vv.z, vv.w};
#pragma unroll
            for (int i = 0; i < 4; i++)
#pragma unroll
                for (int j = 0; j < 4; j++)
                    o[i][j] = fmaf(pa[i], va[j], o[i][j]);
        }
    }

#pragma unroll
    for (int i = 0; i < 4; i++) {
        float inv = 1.f / l_i[i];
        float* op = out + (size_t)(b * SEQ + q0 + r0 + i) * DIM + h * DHEAD + d0;
        *(float4*)op = make_float4(o[i][0] * inv, o[i][1] * inv,
                                   o[i][2] * inv, o[i][3] * inv);
    }
}

// ---------------------------------------------------------------------------
extern "C" void kernel_launch(void* const* d_in, const int* in_sizes, int n_in,
                              void* d_out, int out_size)
{
    const float* x    = (const float*)d_in[0];  // [4, 2048, 512]
    const float* Wqkv = (const float*)d_in[1];  // [1536, 512]
    const float* Wout = (const float*)d_in[2];  // [512, 512]
    float* out = (float*)d_out;                 // [4, 2048, 512]

    float *qkvbuf, *attbuf;
    __nv_bfloat16 *xhi, *xlo, *whi, *wlo, *uhi, *ulo, *ahi, *alo;
    cudaGetSymbolAddress((void**)&qkvbuf, g_qkv);
    cudaGetSymbolAddress((void**)&attbuf, g_att);
    cudaGetSymbolAddress((void**)&xhi, g_xhi);
    cudaGetSymbolAddress((void**)&xlo, g_xlo);
    cudaGetSymbolAddress((void**)&whi, g_whi);
    cudaGetSymbolAddress((void**)&wlo, g_wlo);
    cudaGetSymbolAddress((void**)&uhi, g_uhi);
    cudaGetSymbolAddress((void**)&ulo, g_ulo);
    cudaGetSymbolAddress((void**)&ahi, g_ahi);
    cudaGetSymbolAddress((void**)&alo, g_alo);

    const int smem_flash = 4 * 64 * LD * (int)sizeof(float);
    cudaFuncSetAttribute(flash_attn,
                         cudaFuncAttributeMaxDynamicSharedMemorySize, smem_flash);
    cudaFuncSetAttribute(gemm_mma,
                         cudaFuncAttributeMaxDynamicSharedMemorySize, GEMM_SMEM);

    // Split inputs to hi/lo bf16
    {
        int n4 = MTOT * DIM / 4;
        split_f32<<<(n4 + 255) / 256, 256>>>((const float4*)x, xhi, xlo, n4);
        n4 = QKVC * DIM / 4;
        split_f32<<<(n4 + 255) / 256, 256>>>((const float4*)Wqkv, whi, wlo, n4);
        n4 = DIM * DIM / 4;
        split_f32<<<(n4 + 255) / 256, 256>>>((const float4*)Wout, uhi, ulo, n4);
    }

    // 1) QKV projection on tensor cores: [8192,512] @ [1536,512]^T
    gemm_mma<<<dim3(QKVC / 128, MTOT / 128), 256, GEMM_SMEM>>>(
        xhi, xlo, whi, wlo, qkvbuf, MTOT, QKVC, DIM);

    // 2) Flash attention (fp32, unchanged)
    flash_attn<<<dim3(SEQ / 64, BATCH * HEADS), 256, smem_flash>>>(qkvbuf, attbuf);

    // 3) Split attention output, then out projection on tensor cores
    {
        int n4 = MTOT * DIM / 4;
        split_f32<<<(n4 + 255) / 256, 256>>>((const float4*)attbuf, ahi, alo, n4);
    }
    gemm_mma<<<dim3(DIM / 128, MTOT / 128), 256, GEMM_SMEM>>>(
        ahi, alo, uhi, ulo, out, MTOT, DIM, DIM);
}

// round 4
// speedup vs baseline: 2.7680x; 2.3032x over previous
#include <cuda_runtime.h>
#include <cuda_bf16.h>
#include <cstdint>
#include <math.h>

#define BATCH 4
#define SEQ   2048
#define DIM   512
#define HEADS 8
#define DHEAD 64
#define QKVC  1536
#define MTOT  (BATCH * SEQ)   // 8192

// ---------------------------------------------------------------------------
// Scratch (__device__ globals)
// ---------------------------------------------------------------------------
__device__ __align__(16) __nv_bfloat16 g_xhi[(size_t)MTOT * DIM];
__device__ __align__(16) __nv_bfloat16 g_xlo[(size_t)MTOT * DIM];
__device__ __align__(16) __nv_bfloat16 g_whi[(size_t)QKVC * DIM];
__device__ __align__(16) __nv_bfloat16 g_wlo[(size_t)QKVC * DIM];
__device__ __align__(16) __nv_bfloat16 g_uhi[(size_t)DIM * DIM];
__device__ __align__(16) __nv_bfloat16 g_ulo[(size_t)DIM * DIM];
__device__ __align__(16) __nv_bfloat16 g_qkvhi[(size_t)MTOT * QKVC];
__device__ __align__(16) __nv_bfloat16 g_qkvlo[(size_t)MTOT * QKVC];
__device__ __align__(16) __nv_bfloat16 g_ahi[(size_t)MTOT * DIM];
__device__ __align__(16) __nv_bfloat16 g_alo[(size_t)MTOT * DIM];

// ---------------------------------------------------------------------------
// Helpers
// ---------------------------------------------------------------------------
__device__ __forceinline__ uint32_t smem_u32(const void* p) {
    uint32_t a;
    asm("{ .reg .u64 t; cvta.to.shared.u64 t, %1; cvt.u32.u64 %0, t; }"
        : "=r"(a) : "l"(p));
    return a;
}

__device__ __forceinline__ void ldmatrix_x4(
    uint32_t& r0, uint32_t& r1, uint32_t& r2, uint32_t& r3, uint32_t addr)
{
    asm volatile("ldmatrix.sync.aligned.m8n8.x4.shared.b16 {%0,%1,%2,%3}, [%4];"
                 : "=r"(r0), "=r"(r1), "=r"(r2), "=r"(r3) : "r"(addr));
}

__device__ __forceinline__ void ldmatrix_x4_trans(
    uint32_t& r0, uint32_t& r1, uint32_t& r2, uint32_t& r3, uint32_t addr)
{
    asm volatile("ldmatrix.sync.aligned.m8n8.x4.trans.shared.b16 {%0,%1,%2,%3}, [%4];"
                 : "=r"(r0), "=r"(r1), "=r"(r2), "=r"(r3) : "r"(addr));
}

__device__ __forceinline__ void mma_bf16(
    float* d, uint32_t a0, uint32_t a1, uint32_t a2, uint32_t a3,
    uint32_t b0, uint32_t b1)
{
    asm volatile(
        "mma.sync.aligned.m16n8k16.row.col.f32.bf16.bf16.f32 "
        "{%0,%1,%2,%3}, {%4,%5,%6,%7}, {%8,%9}, {%0,%1,%2,%3};"
        : "+f"(d[0]), "+f"(d[1]), "+f"(d[2]), "+f"(d[3])
        : "r"(a0), "r"(a1), "r"(a2), "r"(a3), "r"(b0), "r"(b1));
}

__device__ __forceinline__ void cp_async16(uint32_t dst, const void* src) {
    asm volatile("cp.async.cg.shared.global [%0], [%1], 16;" :: "r"(dst), "l"(src));
}

// split a float pair into packed bf16x2 hi + bf16x2 lo (x = lower lane)
__device__ __forceinline__ void split_pack(
    float p0, float p1, uint32_t& hi, uint32_t& lo)
{
    __nv_bfloat16 h0 = __float2bfloat16_rn(p0);
    __nv_bfloat16 h1 = __float2bfloat16_rn(p1);
    __nv_bfloat162 hh; hh.x = h0; hh.y = h1;
    hi = *reinterpret_cast<uint32_t*>(&hh);
    float r0 = p0 - __bfloat162float(h0);
    float r1 = p1 - __bfloat162float(h1);
    asm("cvt.rn.bf16x2.f32 %0, %1, %2;" : "=r"(lo) : "f"(r1), "f"(r0));
}

// ---------------------------------------------------------------------------
// fp32 -> (hi, lo) bf16 split
// ---------------------------------------------------------------------------
__global__ __launch_bounds__(256) void split_f32(
    const float4* __restrict__ in, __nv_bfloat16* __restrict__ hi,
    __nv_bfloat16* __restrict__ lo, int n4)
{
    int i = blockIdx.x * 256 + threadIdx.x;
    if (i >= n4) return;
    float4 v = in[i];
    float xs[4] = {v.x, v.y, v.z, v.w};
    __nv_bfloat16 h[4], l[4];
#pragma unroll
    for (int j = 0; j < 4; j++) {
        h[j] = __float2bfloat16_rn(xs[j]);
        l[j] = __float2bfloat16_rn(xs[j] - __bfloat162float(h[j]));
    }
    *(uint2*)(hi + 4 * (size_t)i) = *(uint2*)h;
    *(uint2*)(lo + 4 * (size_t)i) = *(uint2*)l;
}

// ---------------------------------------------------------------------------
// mma.sync split-bf16 GEMM: C = A[M,K] @ B[N,K]^T
// SPLIT=false -> fp32 C;  SPLIT=true -> bf16 hi/lo C (for flash consumption)
// ---------------------------------------------------------------------------
#define LDS_T   40
#define TILE_E  (128 * LDS_T)
#define GEMM_SMEM (2 * 4 * TILE_E * 2)

template <bool SPLIT>
__global__ __launch_bounds__(256, 1) void gemm_mma(
    const __nv_bfloat16* __restrict__ Ahi, const __nv_bfloat16* __restrict__ Alo,
    const __nv_bfloat16* __restrict__ Bhi, const __nv_bfloat16* __restrict__ Blo,
    float* __restrict__ C, __nv_bfloat16* __restrict__ Chi,
    __nv_bfloat16* __restrict__ Clo, int M, int N, int K)
{
    extern __shared__ __nv_bfloat16 sm[];
    const uint32_t sbase = smem_u32(sm);

    const int tid  = threadIdx.x;
    const int wid  = tid >> 5;
    const int lane = tid & 31;
    const int warp_m = wid >> 2;
    const int warp_n = wid & 3;
    const int m0 = blockIdx.y * 128;
    const int n0 = blockIdx.x * 128;

    const __nv_bfloat16* srcs[4] = {
        Ahi + (size_t)m0 * K, Alo + (size_t)m0 * K,
        Bhi + (size_t)n0 * K, Blo + (size_t)n0 * K };

    const int lr   = lane & 15;
    const int kofs = (lane & 16) ? 8 : 0;

    float acc[4][4][4];
#pragma unroll
    for (int mi = 0; mi < 4; mi++)
#pragma unroll
        for (int ni = 0; ni < 4; ni++)
#pragma unroll
            for (int r = 0; r < 4; r++) acc[mi][ni][r] = 0.f;

    const int nchunks = K / 32;

    auto issue_stage = [&](int st, int k0) {
#pragma unroll
        for (int t = 0; t < 4; t++) {
#pragma unroll
            for (int q = 0; q < 2; q++) {
                int v   = tid + q * 256;
                int row = v >> 2;
                int kv  = v & 3;
                uint32_t dst = sbase +
                    (uint32_t)(((st * 4 + t) * TILE_E + row * LDS_T + kv * 8) * 2);
                cp_async16(dst, srcs[t] + (size_t)row * K + k0 + kv * 8);
            }
        }
        asm volatile("cp.async.commit_group;");
    };

    issue_stage(0, 0);

    for (int c = 0; c < nchunks; c++) {
        if (c + 1 < nchunks) {
            issue_stage((c + 1) & 1, (c + 1) * 32);
            asm volatile("cp.async.wait_group 1;");
        } else {
            asm volatile("cp.async.wait_group 0;");
        }
        __syncthreads();

        const uint32_t stb = sbase + (uint32_t)(((c & 1) * 4) * TILE_E * 2);

#pragma unroll
        for (int ks = 0; ks < 32; ks += 16) {
            uint32_t Ahif[4][4], Alof[4][4];
#pragma unroll
            for (int mi = 0; mi < 4; mi++) {
                int row = warp_m * 64 + mi * 16 + lr;
                uint32_t a0 = stb + (uint32_t)((0 * TILE_E + row * LDS_T + ks + kofs) * 2);
                uint32_t a1 = stb + (uint32_t)((1 * TILE_E + row * LDS_T + ks + kofs) * 2);
                ldmatrix_x4(Ahif[mi][0], Ahif[mi][1], Ahif[mi][2], Ahif[mi][3], a0);
                ldmatrix_x4(Alof[mi][0], Alof[mi][1], Alof[mi][2], Alof[mi][3], a1);
            }
            uint32_t Bhif[4][2], Blof[4][2];
#pragma unroll
            for (int bi = 0; bi < 2; bi++) {
                int row = warp_n * 32 + bi * 16 + lr;
                uint32_t b0 = stb + (uint32_t)((2 * TILE_E + row * LDS_T + ks + kofs) * 2);
                uint32_t b1 = stb + (uint32_t)((3 * TILE_E + row * LDS_T + ks + kofs) * 2);
                uint32_t r0, r1, r2, r3;
                ldmatrix_x4(r0, r1, r2, r3, b0);
                Bhif[bi * 2][0] = r0; Bhif[bi * 2][1] = r2;
                Bhif[bi * 2 + 1][0] = r1; Bhif[bi * 2 + 1][1] = r3;
                ldmatrix_x4(r0, r1, r2, r3, b1);
                Blof[bi * 2][0] = r0; Blof[bi * 2][1] = r2;
                Blof[bi * 2 + 1][0] = r1; Blof[bi * 2 + 1][1] = r3;
            }
#pragma unroll
            for (int mi = 0; mi < 4; mi++) {
#pragma unroll
                for (int ni = 0; ni < 4; ni++) {
                    float* d = acc[mi][ni];
                    mma_bf16(d, Ahif[mi][0], Ahif[mi][1], Ahif[mi][2], Ahif[mi][3],
                             Bhif[ni][0], Bhif[ni][1]);
                    mma_bf16(d, Ahif[mi][0], Ahif[mi][1], Ahif[mi][2], Ahif[mi][3],
                             Blof[ni][0], Blof[ni][1]);
                    mma_bf16(d, Alof[mi][0], Alof[mi][1], Alof[mi][2], Alof[mi][3],
                             Bhif[ni][0], Bhif[ni][1]);
                }
            }
        }
        __syncthreads();
    }

    const int g = lane >> 2, tig = lane & 3;
#pragma unroll
    for (int mi = 0; mi < 4; mi++) {
#pragma unroll
        for (int ni = 0; ni < 4; ni++) {
            int row = m0 + warp_m * 64 + mi * 16 + g;
            int col = n0 + warp_n * 32 + ni * 8 + tig * 2;
            float* d = acc[mi][ni];
            if (SPLIT) {
                uint32_t hi, lo;
                split_pack(d[0], d[1], hi, lo);
                *(uint32_t*)&Chi[(size_t)row * N + col] = hi;
                *(uint32_t*)&Clo[(size_t)row * N + col] = lo;
                split_pack(d[2], d[3], hi, lo);
                *(uint32_t*)&Chi[(size_t)(row + 8) * N + col] = hi;
                *(uint32_t*)&Clo[(size_t)(row + 8) * N + col] = lo;
            } else {
                *(float2*)&C[(size_t)row * N + col] = make_float2(d[0], d[1]);
                *(float2*)&C[(size_t)(row + 8) * N + col] = make_float2(d[2], d[3]);
            }
        }
    }
}

// ---------------------------------------------------------------------------
// Tensor-core flash attention (split-bf16, fp32 accumulate)
// BM=128 q/CTA (8 warps x 16 rows), BN=64 keys/iter, D=64.
// ---------------------------------------------------------------------------
#define FLD 72   // smem row stride in bf16 elems (144 B; 9x16B -> conflict-free)
#define FLASH_SMEM ((2 * 128 * FLD + 2 * 4 * 64 * FLD) * 2)   // 110592 B

__global__ __launch_bounds__(256) void flash_mma(
    const __nv_bfloat16* __restrict__ qkvhi,
    const __nv_bfloat16* __restrict__ qkvlo,
    __nv_bfloat16* __restrict__ ohi, __nv_bfloat16* __restrict__ olo)
{
    extern __shared__ __nv_bfloat16 sm[];
    __nv_bfloat16* Qh = sm;
    __nv_bfloat16* Ql = sm + 128 * FLD;
    __nv_bfloat16* KV = sm + 2 * 128 * FLD;   // [stage][Khi,Klo,Vhi,Vlo][64*FLD]

    const int tid  = threadIdx.x;
    const int wid  = tid >> 5;
    const int lane = tid & 31;
    const int g    = lane >> 2;
    const int tq   = lane & 3;
    const int lr   = lane & 15;
    const int kofs = (lane & 16) ? 8 : 0;

    const int b  = blockIdx.y >> 3;
    const int h  = blockIdx.y & 7;
    const int q0 = blockIdx.x * 128;
    const size_t qrowg = (size_t)(b * SEQ + q0);

    // ---- issue Q tile + K/V tile 0 (one cp.async group) ----
    {
#pragma unroll
        for (int q = 0; q < 4; q++) {
            int v = tid + q * 256;          // 0..1023
            int row = v >> 3, seg = v & 7;
            const size_t goff = (qrowg + row) * QKVC + h * DHEAD + seg * 8;
            cp_async16(smem_u32(Qh + row * FLD + seg * 8), qkvhi + goff);
            cp_async16(smem_u32(Ql + row * FLD + seg * 8), qkvlo + goff);
        }
    }
    auto issue_kv = [&](int st, int ktile) {
        const size_t krow = (size_t)(b * SEQ + ktile * 64);
        __nv_bfloat16* dst0 = KV + st * 4 * 64 * FLD;
#pragma unroll
        for (int t = 0; t < 4; t++) {
            const __nv_bfloat16* src = (t == 0 || t == 2) ? qkvhi : qkvlo;
            const int colb = (t < 2 ? 512 : 1024) + h * DHEAD;
#pragma unroll
            for (int q = 0; q < 2; q++) {
                int v = tid + q * 256;       // 0..511
                int row = v >> 3, seg = v & 7;
                cp_async16(smem_u32(dst0 + t * 64 * FLD + row * FLD + seg * 8),
                           src + (krow + row) * QKVC + colb + seg * 8);
            }
        }
    };
    issue_kv(0, 0);
    asm volatile("cp.async.commit_group;");

    float m_i[2] = {-INFINITY, -INFINITY};
    float l_i[2] = {0.f, 0.f};
    float O[8][4];
#pragma unroll
    for (int j = 0; j < 8; j++)
#pragma unroll
        for (int r = 0; r < 4; r++) O[j][r] = 0.f;

    const float CSC = 0.125f * 1.4426950408889634f;  // scale * log2(e)

    for (int c = 0; c < SEQ / 64; c++) {
        if (c + 1 < SEQ / 64) {
            issue_kv((c + 1) & 1, c + 1);
            asm volatile("cp.async.commit_group;");
            asm volatile("cp.async.wait_group 1;");
        } else {
            asm volatile("cp.async.wait_group 0;");
        }
        __syncthreads();

        const __nv_bfloat16* Kh = KV + (c & 1) * 4 * 64 * FLD;
        const __nv_bfloat16* Kl = Kh + 64 * FLD;
        const __nv_bfloat16* Vh = Kl + 64 * FLD;
        const __nv_bfloat16* Vl = Vh + 64 * FLD;

        // ---- S = Q @ K^T (3 split terms) ----
        float S[8][4];
#pragma unroll
        for (int j = 0; j < 8; j++)
#pragma unroll
            for (int r = 0; r < 4; r++) S[j][r] = 0.f;

#pragma unroll
        for (int kk = 0; kk < 4; kk++) {
            uint32_t qh[4], ql[4];
            ldmatrix_x4(qh[0], qh[1], qh[2], qh[3],
                smem_u32(Qh + (wid * 16 + lr) * FLD + kk * 16 + kofs));
            ldmatrix_x4(ql[0], ql[1], ql[2], ql[3],
                smem_u32(Ql + (wid * 16 + lr) * FLD + kk * 16 + kofs));
#pragma unroll
            for (int bi = 0; bi < 4; bi++) {
                uint32_t kh0, kh1, kh2, kh3, kl0, kl1, kl2, kl3;
                ldmatrix_x4(kh0, kh1, kh2, kh3,
                    smem_u32(Kh + (bi * 16 + lr) * FLD + kk * 16 + kofs));
                ldmatrix_x4(kl0, kl1, kl2, kl3,
                    smem_u32(Kl + (bi * 16 + lr) * FLD + kk * 16 + kofs));
                mma_bf16(S[bi * 2],     qh[0], qh[1], qh[2], qh[3], kh0, kh2);
                mma_bf16(S[bi * 2],     qh[0], qh[1], qh[2], qh[3], kl0, kl2);
                mma_bf16(S[bi * 2],     ql[0], ql[1], ql[2], ql[3], kh0, kh2);
                mma_bf16(S[bi * 2 + 1], qh[0], qh[1], qh[2], qh[3], kh1, kh3);
                mma_bf16(S[bi * 2 + 1], qh[0], qh[1], qh[2], qh[3], kl1, kl3);
                mma_bf16(S[bi * 2 + 1], ql[0], ql[1], ql[2], ql[3], kh1, kh3);
            }
        }

        // ---- online softmax (rows g and g+8; 4 lanes per row) ----
#pragma unroll
        for (int j = 0; j < 8; j++)
#pragma unroll
            for (int r = 0; r < 4; r++) S[j][r] *= CSC;

#pragma unroll
        for (int r = 0; r < 2; r++) {
            float mloc = -INFINITY;
#pragma unroll
            for (int j = 0; j < 8; j++)
                mloc = fmaxf(mloc, fmaxf(S[j][2 * r], S[j][2 * r + 1]));
            mloc = fmaxf(mloc, __shfl_xor_sync(0xffffffffu, mloc, 1));
            mloc = fmaxf(mloc, __shfl_xor_sync(0xffffffffu, mloc, 2));
            float mnew = fmaxf(m_i[r], mloc);
            float corr = exp2f(m_i[r] - mnew);
            m_i[r] = mnew;
            float ps = 0.f;
#pragma unroll
            for (int j = 0; j < 8; j++) {
                float p0 = exp2f(S[j][2 * r] - mnew);
                float p1 = exp2f(S[j][2 * r + 1] - mnew);
                S[j][2 * r] = p0; S[j][2 * r + 1] = p1;
                ps += p0 + p1;
            }
            ps += __shfl_xor_sync(0xffffffffu, ps, 1);
            ps += __shfl_xor_sync(0xffffffffu, ps, 2);
            l_i[r] = l_i[r] * corr + ps;
#pragma unroll
            for (int j = 0; j < 8; j++) {
                O[j][2 * r] *= corr; O[j][2 * r + 1] *= corr;
            }
        }

        // ---- O += P @ V (3 split terms, P repacked thread-locally) ----
#pragma unroll
        for (int kk = 0; kk < 4; kk++) {
            uint32_t pah[4], pal[4];
            split_pack(S[2 * kk][0],     S[2 * kk][1],     pah[0], pal[0]);
            split_pack(S[2 * kk][2],     S[2 * kk][3],     pah[1], pal[1]);
            split_pack(S[2 * kk + 1][0], S[2 * kk + 1][1], pah[2], pal[2]);
            split_pack(S[2 * kk + 1][2], S[2 * kk + 1][3], pah[3], pal[3]);

            const int mi = lane >> 3, ri = lane & 7;
            const int key = kk * 16 + ((mi & 1) << 3) + ri;
            const int dimb = (mi >> 1) << 3;
#pragma unroll
            for (int jj = 0; jj < 4; jj++) {
                uint32_t t0, t1, t2, t3, u0, u1, u2, u3;
                ldmatrix_x4_trans(t0, t1, t2, t3,
                    smem_u32(Vh + key * FLD + jj * 16 + dimb));
                ldmatrix_x4_trans(u0, u1, u2, u3,
                    smem_u32(Vl + key * FLD + jj * 16 + dimb));
                mma_bf16(O[jj * 2],     pah[0], pah[1], pah[2], pah[3], t0, t1);
                mma_bf16(O[jj * 2],     pah[0], pah[1], pah[2], pah[3], u0, u1);
                mma_bf16(O[jj * 2],     pal[0], pal[1], pal[2], pal[3], t0, t1);
                mma_bf16(O[jj * 2 + 1], pah[0], pah[1], pah[2], pah[3], t2, t3);
                mma_bf16(O[jj * 2 + 1], pah[0], pah[1], pah[2], pah[3], u2, u3);
                mma_bf16(O[jj * 2 + 1], pal[0], pal[1], pal[2], pal[3], t2, t3);
            }
        }
        __syncthreads();   // reads done before next issue overwrites other stage
    }

    // ---- epilogue: normalize, write hi/lo bf16 ----
    const float inv0 = 1.f / l_i[0];
    const float inv1 = 1.f / l_i[1];
    const size_t row0 = qrowg + wid * 16 + g;
#pragma unroll
    for (int j = 0; j < 8; j++) {
        const int col = h * DHEAD + j * 8 + tq * 2;
        uint32_t hi, lo;
        split_pack(O[j][0] * inv0, O[j][1] * inv0, hi, lo);
        *(uint32_t*)&ohi[row0 * DIM + col] = hi;
        *(uint32_t*)&olo[row0 * DIM + col] = lo;
        split_pack(O[j][2] * inv1, O[j][3] * inv1, hi, lo);
        *(uint32_t*)&ohi[(row0 + 8) * DIM + col] = hi;
        *(uint32_t*)&olo[(row0 + 8) * DIM + col] = lo;
    }
}

// ---------------------------------------------------------------------------
extern "C" void kernel_launch(void* const* d_in, const int* in_sizes, int n_in,
                              void* d_out, int out_size)
{
    const float* x    = (const float*)d_in[0];
    const float* Wqkv = (const float*)d_in[1];
    const float* Wout = (const float*)d_in[2];
    float* out = (float*)d_out;

    __nv_bfloat16 *xhi, *xlo, *whi, *wlo, *uhi, *ulo, *qhi, *qlo, *ahi, *alo;
    cudaGetSymbolAddress((void**)&xhi, g_xhi);
    cudaGetSymbolAddress((void**)&xlo, g_xlo);
    cudaGetSymbolAddress((void**)&whi, g_whi);
    cudaGetSymbolAddress((void**)&wlo, g_wlo);
    cudaGetSymbolAddress((void**)&uhi, g_uhi);
    cudaGetSymbolAddress((void**)&ulo, g_ulo);
    cudaGetSymbolAddress((void**)&qhi, g_qkvhi);
    cudaGetSymbolAddress((void**)&qlo, g_qkvlo);
    cudaGetSymbolAddress((void**)&ahi, g_ahi);
    cudaGetSymbolAddress((void**)&alo, g_alo);

    cudaFuncSetAttribute(gemm_mma<true>,
                         cudaFuncAttributeMaxDynamicSharedMemorySize, GEMM_SMEM);
    cudaFuncSetAttribute(gemm_mma<false>,
                         cudaFuncAttributeMaxDynamicSharedMemorySize, GEMM_SMEM);
    cudaFuncSetAttribute(flash_mma,
                         cudaFuncAttributeMaxDynamicSharedMemorySize, FLASH_SMEM);

    // splits
    {
        int n4 = MTOT * DIM / 4;
        split_f32<<<(n4 + 255) / 256, 256>>>((const float4*)x, xhi, xlo, n4);
        n4 = QKVC * DIM / 4;
        split_f32<<<(n4 + 255) / 256, 256>>>((const float4*)Wqkv, whi, wlo, n4);
        n4 = DIM * DIM / 4;
        split_f32<<<(n4 + 255) / 256, 256>>>((const float4*)Wout, uhi, ulo, n4);
    }

    // 1) QKV projection -> hi/lo bf16 qkv
    gemm_mma<true><<<dim3(QKVC / 128, MTOT / 128), 256, GEMM_SMEM>>>(
        xhi, xlo, whi, wlo, nullptr, qhi, qlo, MTOT, QKVC, DIM);

    // 2) tensor-core flash attention -> hi/lo bf16 attention output
    flash_mma<<<dim3(SEQ / 128, BATCH * HEADS), 256, FLASH_SMEM>>>(
        qhi, qlo, ahi, alo);

    // 3) out projection -> fp32 final output
    gemm_mma<false><<<dim3(DIM / 128, MTOT / 128), 256, GEMM_SMEM>>>(
        ahi, alo, uhi, ulo, out, nullptr, nullptr, MTOT, DIM, DIM);
}